// round 1
// baseline (speedup 1.0000x reference)
#include <cuda_runtime.h>
#include <math.h>

#define NMAX 100000
#define EMAX 1600000
#define FD 128
#define HD 128
#define CD 40
#define NLAY 4

// ---- static device scratch (no allocations allowed) ----
__device__ float g_xw[(size_t)NMAX * HD];             // current layer x@W
__device__ float g_agg[NLAY][(size_t)NMAX * HD];      // per-layer pre-BN conv output
__device__ int   g_cnt[NMAX];
__device__ float g_dinv[NMAX];
__device__ int   g_off[NMAX + 1];
__device__ int   g_cur[NMAX];
__device__ int   g_csrc[EMAX];
__device__ float g_cval[EMAX];
__device__ float g_stats[NLAY][2 * HD];               // col sums / sumsq
__device__ float g_scale[NLAY][HD];                   // fused BN scale
__device__ float g_sbias[NLAY][HD];                   // fused BN bias
__device__ float g_outb[(size_t)NMAX * CD];           // pre-softmax logits

// ---------------------------------------------------------------------------
__global__ void k_init(int n) {
    int i = blockIdx.x * blockDim.x + threadIdx.x;
    if (i < n) g_cnt[i] = 0;
    if (i < NLAY * 2 * HD) ((float*)g_stats)[i] = 0.0f;
}

__global__ void k_hist(const int* __restrict__ dst, int e) {
    int i = blockIdx.x * blockDim.x + threadIdx.x;
    if (i < e) atomicAdd(&g_cnt[dst[i]], 1);
}

// single-block scan: offsets, cursor init, dinv
__global__ void k_scan(int n) {
    __shared__ int sp[1024];
    int t = threadIdx.x;
    int chunk = (n + 1023) >> 10;
    int beg = t * chunk;
    int end = min(beg + chunk, n);
    int s = 0;
    for (int j = beg; j < end; j++) s += g_cnt[j];
    sp[t] = s;
    __syncthreads();
    for (int d = 1; d < 1024; d <<= 1) {
        int tmp = (t >= d) ? sp[t - d] : 0;
        __syncthreads();
        sp[t] += tmp;
        __syncthreads();
    }
    int base = sp[t] - s;  // exclusive
    for (int j = beg; j < end; j++) {
        g_off[j] = base;
        g_cur[j] = base;
        g_dinv[j] = rsqrtf((float)g_cnt[j] + 2.0f);
        base += g_cnt[j];
    }
    if (end == n) g_off[n] = base;
}

__global__ void k_fill(const int* __restrict__ src, const int* __restrict__ dst, int e) {
    int i = blockIdx.x * blockDim.x + threadIdx.x;
    if (i < e) {
        int d = dst[i];
        int s = src[i];
        int p = atomicAdd(&g_cur[d], 1);
        g_csrc[p] = s;
        g_cval[p] = g_dinv[s];
    }
}

// ---------------------------------------------------------------------------
// SGEMM: g_xw[n,128] = A[n,128] @ W[128,128]
// A = x (layer 0) or relu(g_agg[layer-1]*scale+bias) fused on load.
__global__ __launch_bounds__(256) void k_gemm(const float* __restrict__ x,
                                              const float* __restrict__ W,
                                              int layer, int n) {
    __shared__ __align__(16) float As[8][128];
    __shared__ __align__(16) float Bs[8][128];
    const float* A  = (layer == 0) ? x : g_agg[layer - 1];
    const float* sc = (layer > 0) ? g_scale[layer - 1] : 0;
    const float* sb = (layer > 0) ? g_sbias[layer - 1] : 0;
    int tid  = threadIdx.x;
    int trow = tid >> 4, tcol = tid & 15;
    int arow = tid >> 1, acol = (tid & 1) * 4;
    int brow = tid >> 5, bcol = (tid & 31) * 4;
    int row0 = blockIdx.x * 128;

    float acc[8][8];
#pragma unroll
    for (int m = 0; m < 8; m++)
#pragma unroll
        for (int q = 0; q < 8; q++) acc[m][q] = 0.0f;

    for (int k0 = 0; k0 < 128; k0 += 8) {
        int gr = row0 + arow;
        float4 a4 = make_float4(0.f, 0.f, 0.f, 0.f);
        if (gr < n) a4 = *(const float4*)(A + (size_t)gr * HD + k0 + acol);
        if (layer > 0) {
            int kb = k0 + acol;
            a4.x = fmaxf(fmaf(a4.x, sc[kb + 0], sb[kb + 0]), 0.f);
            a4.y = fmaxf(fmaf(a4.y, sc[kb + 1], sb[kb + 1]), 0.f);
            a4.z = fmaxf(fmaf(a4.z, sc[kb + 2], sb[kb + 2]), 0.f);
            a4.w = fmaxf(fmaf(a4.w, sc[kb + 3], sb[kb + 3]), 0.f);
        }
        As[acol + 0][arow] = a4.x;
        As[acol + 1][arow] = a4.y;
        As[acol + 2][arow] = a4.z;
        As[acol + 3][arow] = a4.w;
        *(float4*)&Bs[brow][bcol] =
            *(const float4*)(W + (size_t)(k0 + brow) * HD + bcol);
        __syncthreads();
#pragma unroll
        for (int k = 0; k < 8; k++) {
            float4 ra0 = *(const float4*)&As[k][trow * 8];
            float4 ra1 = *(const float4*)&As[k][trow * 8 + 4];
            float4 rb0 = *(const float4*)&Bs[k][tcol * 8];
            float4 rb1 = *(const float4*)&Bs[k][tcol * 8 + 4];
            float ra[8] = {ra0.x, ra0.y, ra0.z, ra0.w, ra1.x, ra1.y, ra1.z, ra1.w};
            float rb[8] = {rb0.x, rb0.y, rb0.z, rb0.w, rb1.x, rb1.y, rb1.z, rb1.w};
#pragma unroll
            for (int m = 0; m < 8; m++)
#pragma unroll
                for (int q = 0; q < 8; q++) acc[m][q] = fmaf(ra[m], rb[q], acc[m][q]);
        }
        __syncthreads();
    }
#pragma unroll
    for (int m = 0; m < 8; m++) {
        int r = row0 + trow * 8 + m;
        if (r < n) {
            *(float4*)(g_xw + (size_t)r * HD + tcol * 8) =
                make_float4(acc[m][0], acc[m][1], acc[m][2], acc[m][3]);
            *(float4*)(g_xw + (size_t)r * HD + tcol * 8 + 4) =
                make_float4(acc[m][4], acc[m][5], acc[m][6], acc[m][7]);
        }
    }
}

// ---------------------------------------------------------------------------
// Aggregation: warp per node; lane owns 4 columns. Also accumulates BN stats.
__global__ __launch_bounds__(256) void k_agg(int layer, const float* __restrict__ convb, int n) {
    __shared__ float s_sum[128], s_sq[128];
    int tid = threadIdx.x;
    if (tid < 128) { s_sum[tid] = 0.f; s_sq[tid] = 0.f; }
    __syncthreads();

    int lane = tid & 31;
    int warp = tid >> 5;
    int c4 = lane * 4;
    float4 b4 = *(const float4*)(convb + c4);
    float* out = g_agg[layer];

    int gw = blockIdx.x * 8 + warp;
    int nw = gridDim.x * 8;

    float ls0 = 0.f, ls1 = 0.f, ls2 = 0.f, ls3 = 0.f;
    float lq0 = 0.f, lq1 = 0.f, lq2 = 0.f, lq3 = 0.f;

    for (int v = gw; v < n; v += nw) {
        int r0 = g_off[v], r1 = g_off[v + 1];
        float dv = g_dinv[v];
        float a0 = 0.f, a1 = 0.f, a2 = 0.f, a3 = 0.f;
        int j = r0;
        for (; j + 1 < r1; j += 2) {
            int   s0 = g_csrc[j],   s1 = g_csrc[j + 1];
            float w0 = g_cval[j],   w1 = g_cval[j + 1];
            float4 x0 = *(const float4*)(g_xw + (size_t)s0 * HD + c4);
            float4 x1 = *(const float4*)(g_xw + (size_t)s1 * HD + c4);
            a0 = fmaf(w0, x0.x, a0); a1 = fmaf(w0, x0.y, a1);
            a2 = fmaf(w0, x0.z, a2); a3 = fmaf(w0, x0.w, a3);
            a0 = fmaf(w1, x1.x, a0); a1 = fmaf(w1, x1.y, a1);
            a2 = fmaf(w1, x1.z, a2); a3 = fmaf(w1, x1.w, a3);
        }
        if (j < r1) {
            int s0 = g_csrc[j]; float w0 = g_cval[j];
            float4 x0 = *(const float4*)(g_xw + (size_t)s0 * HD + c4);
            a0 = fmaf(w0, x0.x, a0); a1 = fmaf(w0, x0.y, a1);
            a2 = fmaf(w0, x0.z, a2); a3 = fmaf(w0, x0.w, a3);
        }
        float4 xv = *(const float4*)(g_xw + (size_t)v * HD + c4);
        float t2 = 2.f * dv * dv;
        a0 = fmaf(dv, a0, fmaf(t2, xv.x, b4.x));
        a1 = fmaf(dv, a1, fmaf(t2, xv.y, b4.y));
        a2 = fmaf(dv, a2, fmaf(t2, xv.z, b4.z));
        a3 = fmaf(dv, a3, fmaf(t2, xv.w, b4.w));
        *(float4*)(out + (size_t)v * HD + c4) = make_float4(a0, a1, a2, a3);
        ls0 += a0; ls1 += a1; ls2 += a2; ls3 += a3;
        lq0 = fmaf(a0, a0, lq0); lq1 = fmaf(a1, a1, lq1);
        lq2 = fmaf(a2, a2, lq2); lq3 = fmaf(a3, a3, lq3);
    }
    atomicAdd(&s_sum[c4 + 0], ls0); atomicAdd(&s_sum[c4 + 1], ls1);
    atomicAdd(&s_sum[c4 + 2], ls2); atomicAdd(&s_sum[c4 + 3], ls3);
    atomicAdd(&s_sq[c4 + 0], lq0);  atomicAdd(&s_sq[c4 + 1], lq1);
    atomicAdd(&s_sq[c4 + 2], lq2);  atomicAdd(&s_sq[c4 + 3], lq3);
    __syncthreads();
    if (tid < 128) {
        atomicAdd(&g_stats[layer][tid], s_sum[tid]);
        atomicAdd(&g_stats[layer][128 + tid], s_sq[tid]);
    }
}

// ---------------------------------------------------------------------------
__global__ void k_fin(const float* __restrict__ bn_g, const float* __restrict__ bn_b,
                      int layer, int n) {
    int t = threadIdx.x;  // 128
    float sum = g_stats[layer][t];
    float sq  = g_stats[layer][t + 128];
    float inv_n = 1.0f / (float)n;
    float mean = sum * inv_n;
    float var  = fmaxf(sq * inv_n - mean * mean, 0.f);
    float s = bn_g[layer * HD + t] * rsqrtf(var + 1e-5f);
    g_scale[layer][t] = s;
    g_sbias[layer][t] = bn_b[layer * HD + t] - mean * s;
}

// ---------------------------------------------------------------------------
// JK head: g_outb[n,40] = sum_i relu_bn(h_i) @ fc_w[i] + sum_i fc_b[i]
// Single GEMM over concatenated K=640, BN+ReLU fused on A load.
__global__ __launch_bounds__(256) void k_jk(const float* __restrict__ x,
                                            const float* __restrict__ fw,
                                            const float* __restrict__ fb, int n) {
    __shared__ __align__(16) float As[16][128];
    __shared__ __align__(16) float Bs[16][40];
    __shared__ float bsum[40];
    int tid = threadIdx.x;
    if (tid < 40) {
        float b = 0.f;
        for (int i = 0; i < NLAY + 1; i++) b += fb[i * CD + tid];
        bsum[tid] = b;
    }
    int trow = tid >> 3, tcol = tid & 7;
    int row0 = blockIdx.x * 128;
    float acc[4][5];
#pragma unroll
    for (int m = 0; m < 4; m++)
#pragma unroll
        for (int c = 0; c < 5; c++) acc[m][c] = 0.f;

    for (int k0 = 0; k0 < 640; k0 += 16) {
        int L = k0 >> 7;
        int kbase = k0 & 127;
        const float* A = (L == 0) ? x : g_agg[L - 1];
#pragma unroll
        for (int v = 0; v < 2; v++) {
            int id = tid + v * 256;
            int r = id >> 2;
            int kq = (id & 3) * 4;
            int gr = row0 + r;
            float4 a4 = make_float4(0.f, 0.f, 0.f, 0.f);
            if (gr < n) a4 = *(const float4*)(A + (size_t)gr * HD + kbase + kq);
            if (L > 0) {
                int kk = kbase + kq;
                a4.x = fmaxf(fmaf(a4.x, g_scale[L - 1][kk + 0], g_sbias[L - 1][kk + 0]), 0.f);
                a4.y = fmaxf(fmaf(a4.y, g_scale[L - 1][kk + 1], g_sbias[L - 1][kk + 1]), 0.f);
                a4.z = fmaxf(fmaf(a4.z, g_scale[L - 1][kk + 2], g_sbias[L - 1][kk + 2]), 0.f);
                a4.w = fmaxf(fmaf(a4.w, g_scale[L - 1][kk + 3], g_sbias[L - 1][kk + 3]), 0.f);
            }
            As[kq + 0][r] = a4.x;
            As[kq + 1][r] = a4.y;
            As[kq + 2][r] = a4.z;
            As[kq + 3][r] = a4.w;
        }
        if (tid < 160) {
            int kr = tid / 10;
            int nc = (tid % 10) * 4;
            int kk = kbase + kr;
            *(float4*)&Bs[kr][nc] =
                *(const float4*)(fw + ((size_t)L * HD + kk) * CD + nc);
        }
        __syncthreads();
#pragma unroll
        for (int k = 0; k < 16; k++) {
            float ra[4], rb[5];
#pragma unroll
            for (int m = 0; m < 4; m++) ra[m] = As[k][trow * 4 + m];
#pragma unroll
            for (int c = 0; c < 5; c++) rb[c] = Bs[k][tcol * 5 + c];
#pragma unroll
            for (int m = 0; m < 4; m++)
#pragma unroll
                for (int c = 0; c < 5; c++) acc[m][c] = fmaf(ra[m], rb[c], acc[m][c]);
        }
        __syncthreads();
    }
#pragma unroll
    for (int m = 0; m < 4; m++) {
        int r = row0 + trow * 4 + m;
        if (r < n) {
#pragma unroll
            for (int c = 0; c < 5; c++)
                g_outb[(size_t)r * CD + tcol * 5 + c] = acc[m][c] + bsum[tcol * 5 + c];
        }
    }
}

// ---------------------------------------------------------------------------
__global__ void k_lsm(float* __restrict__ out, int n) {
    int gw = (blockIdx.x * blockDim.x + threadIdx.x) >> 5;
    int lane = threadIdx.x & 31;
    if (gw >= n) return;
    const float* r = g_outb + (size_t)gw * CD;
    float v0 = r[lane];
    float v1 = (lane < 8) ? r[32 + lane] : -INFINITY;
    float m = fmaxf(v0, v1);
#pragma unroll
    for (int d = 16; d > 0; d >>= 1) m = fmaxf(m, __shfl_xor_sync(0xffffffffu, m, d));
    float s = expf(v0 - m) + ((lane < 8) ? expf(v1 - m) : 0.f);
#pragma unroll
    for (int d = 16; d > 0; d >>= 1) s += __shfl_xor_sync(0xffffffffu, s, d);
    float ls = logf(s);
    out[(size_t)gw * CD + lane] = v0 - m - ls;
    if (lane < 8) out[(size_t)gw * CD + 32 + lane] = v1 - m - ls;
}

// ---------------------------------------------------------------------------
extern "C" void kernel_launch(void* const* d_in, const int* in_sizes, int n_in,
                              void* d_out, int out_size) {
    const float* x      = (const float*)d_in[0];
    const int*   ei     = (const int*)d_in[1];
    const float* conv_w = (const float*)d_in[2];
    const float* conv_b = (const float*)d_in[3];
    const float* bn_g   = (const float*)d_in[4];
    const float* bn_b   = (const float*)d_in[5];
    const float* fc_w   = (const float*)d_in[6];
    const float* fc_b   = (const float*)d_in[7];
    int n = in_sizes[0] / FD;
    int e = in_sizes[1] / 2;
    const int* src = ei;
    const int* dst = ei + e;

    k_init<<<(n + 255) / 256, 256>>>(n);
    k_hist<<<(e + 255) / 256, 256>>>(dst, e);
    k_scan<<<1, 1024>>>(n);
    k_fill<<<(e + 255) / 256, 256>>>(src, dst, e);

    int gblocks = (n + 127) / 128;
    for (int l = 0; l < NLAY; l++) {
        k_gemm<<<gblocks, 256>>>(x, conv_w + (size_t)l * FD * HD, l, n);
        k_agg<<<1480, 256>>>(l, conv_b + (size_t)l * HD, n);
        k_fin<<<1, 128>>>(bn_g, bn_b, l, n);
    }
    k_jk<<<gblocks, 256>>>(x, fc_w, fc_b, n);
    k_lsm<<<(n * 32 + 255) / 256, 256>>>((float*)d_out, n);
}